// round 9
// baseline (speedup 1.0000x reference)
#include <cuda_runtime.h>
#include <cuda_fp16.h>

#define LEAK  0.1f
#define BNEPS 1e-5f

#define NB    64
#define HW    361            // 19*19
#define H19   19
#define C2IN  1280
#define C2K   11520          // 1280*9
#define KO    600
#define KOP   640
#define NPIX  (NB * HW)      // 23104

#define SROW  20             // smem row stride in u32 (80 B)
#define AHw   0              // word offsets of the 4 planes in a stage
#define ALw   2560
#define BHw   5120
#define BLw   7680
#define STG   10240          // u32 per stage (40960 B)
#define SMEMB (2 * STG * 4)  // 81920 bytes

// ---------------- device scratch ----------------
__device__ float g_w1t[512 * 64];
__device__ float g_s1[64],  g_h1[64];
__device__ float g_s2[1024], g_h2[1024];
__device__ float g_cb[KO];
__device__ unsigned g_xp  [(size_t)C2IN * NPIX];   // conv2 input (h|l<<16) fp16 pairs [c][gpix]
__device__ unsigned g_prep[(size_t)1024 * NPIX];   // det input pairs [c][gpix]
__device__ __align__(16) __half g_w2h[(size_t)1024 * C2K];  // K-order r*1280+c
__device__ __align__(16) __half g_w2l[(size_t)1024 * C2K];
__device__ __align__(16) __half g_rwh[(size_t)KOP * 1024];
__device__ __align__(16) __half g_rwl[(size_t)KOP * 1024];

__device__ __forceinline__ unsigned packpair(float x)
{
    __half h = __float2half_rn(x);
    float r = x - __half2float(h);
    __half l = __float2half_rn(r);
    return ((unsigned)__half_as_ushort(l) << 16) | (unsigned)__half_as_ushort(h);
}

// ---------------- cp.async helpers ----------------
__device__ __forceinline__ void cp16(void* smem, const void* g)
{
    unsigned sa = (unsigned)__cvta_generic_to_shared(smem);
    asm volatile("cp.async.cg.shared.global [%0], [%1], 16;\n" :: "r"(sa), "l"(g));
}
__device__ __forceinline__ void cp_commit() { asm volatile("cp.async.commit_group;\n"); }
__device__ __forceinline__ void cp_wait0()  { asm volatile("cp.async.wait_group 0;\n"); }

// ---------------- prep ----------------
__global__ void prep_kernel(const float* __restrict__ w1,
                            const float* __restrict__ g1, const float* __restrict__ b1,
                            const float* __restrict__ m1, const float* __restrict__ v1,
                            const float* __restrict__ g2, const float* __restrict__ b2,
                            const float* __restrict__ m2, const float* __restrict__ v2,
                            const float* __restrict__ rw, const float* __restrict__ w2)
{
    long long i = (long long)blockIdx.x * blockDim.x + threadIdx.x;
    if (i < (long long)1024 * C2K) {
        int co = (int)(i / C2K);
        int t  = (int)(i - (long long)co * C2K);
        int r  = t / C2IN;
        int c  = t - r * C2IN;
        float x = w2[(size_t)co * C2K + c * 9 + r];
        __half h = __float2half_rn(x);
        g_w2h[i] = h;
        g_w2l[i] = __float2half_rn(x - __half2float(h));
    }
    if (i < (long long)KOP * 1024) {
        int m = (int)(i >> 10), c = (int)(i & 1023);
        float x = (m < KO) ? rw[m * 1025 + c] : 0.f;
        __half h = __float2half_rn(x);
        g_rwh[i] = h;
        g_rwl[i] = __float2half_rn(x - __half2float(h));
    }
    if (i < 512 * 64) {
        int k = (int)(i >> 6), co = (int)(i & 63);
        g_w1t[i] = w1[co * 512 + k];
    }
    if (i < KO)   g_cb[i] = rw[i * 1025 + 1024];
    if (i < 64)   { float s = g1[i] * rsqrtf(v1[i] + BNEPS); g_s1[i] = s; g_h1[i] = b1[i] - m1[i] * s; }
    if (i < 1024) { float s = g2[i] * rsqrtf(v2[i] + BNEPS); g_s2[i] = s; g_h2[i] = b2[i] - m2[i] * s; }
}

__global__ void feat0_split(const float* __restrict__ feat0)
{
    long long i = (long long)blockIdx.x * blockDim.x + threadIdx.x;
    if (i < (long long)NB * 1024 * HW) {
        int hw = (int)(i % HW);
        long long t = i / HW;
        int c = (int)(t & 1023);
        int b = (int)(t >> 10);
        g_xp[(size_t)(256 + c) * NPIX + b * HW + hw] = packpair(feat0[i]);
    }
}

// ---------------- conv1 (unchanged structure) ----------------
__global__ __launch_bounds__(256) void conv1_kernel(const float* __restrict__ feat1)
{
    __shared__ __align__(16) float s_in[512][16];
    __shared__ float s_w[64][64];

    const int b    = blockIdx.y;
    const int base = blockIdx.x * 16;
    const float* f = feat1 + (size_t)b * 512 * 1444;

    for (int idx = threadIdx.x; idx < 512 * 16; idx += 256) {
        int p = idx & 15, k = idx >> 4;
        int pix = base + p;
        s_in[k][p] = (pix < 1444) ? f[k * 1444 + pix] : 0.f;
    }

    const int co = threadIdx.x & 63;
    const int pq = threadIdx.x >> 6;
    float acc[4] = {0.f, 0.f, 0.f, 0.f};

    for (int kc = 0; kc < 512; kc += 64) {
        __syncthreads();
        for (int idx = threadIdx.x; idx < 64 * 64; idx += 256)
            s_w[idx >> 6][idx & 63] = g_w1t[(kc + (idx >> 6)) * 64 + (idx & 63)];
        __syncthreads();
        #pragma unroll
        for (int kk = 0; kk < 64; kk++) {
            float  w = s_w[kk][co];
            float4 v = *(const float4*)&s_in[kc + kk][pq * 4];
            acc[0] += v.x * w; acc[1] += v.y * w;
            acc[2] += v.z * w; acc[3] += v.w * w;
        }
    }

    const float s = g_s1[co], hh = g_h1[co];
    #pragma unroll
    for (int j = 0; j < 4; j++) {
        int pix = base + pq * 4 + j;
        if (pix < 1444) {
            float y = acc[j] * s + hh;
            y = (y > 0.f) ? y : LEAK * y;
            int h38 = pix / 38, w38 = pix - h38 * 38;
            int cc  = ((h38 & 1) * 2 + (w38 & 1)) * 64 + co;
            int gp  = b * HW + (h38 >> 1) * H19 + (w38 >> 1);
            g_xp[(size_t)cc * NPIX + gp] = packpair(y);
        }
    }
}

// ---------------- mma / ldmatrix helpers ----------------
__device__ __forceinline__ void mma16816(float* d, const unsigned* a, const unsigned* b)
{
    asm volatile(
        "mma.sync.aligned.m16n8k16.row.col.f32.f16.f16.f32 "
        "{%0,%1,%2,%3},{%4,%5,%6,%7},{%8,%9},{%0,%1,%2,%3};"
        : "+f"(d[0]), "+f"(d[1]), "+f"(d[2]), "+f"(d[3])
        : "r"(a[0]), "r"(a[1]), "r"(a[2]), "r"(a[3]), "r"(b[0]), "r"(b[1]));
}

__device__ __forceinline__ void ldsm4(unsigned& r0, unsigned& r1, unsigned& r2, unsigned& r3,
                                      unsigned saddr)
{
    asm volatile("ldmatrix.sync.aligned.m8n8.x4.shared.b16 {%0,%1,%2,%3}, [%4];"
                 : "=r"(r0), "=r"(r1), "=r"(r2), "=r"(r3) : "r"(saddr));
}

// fp16 3-pass (hh + hl + lh) over K=32, ldmatrix-fed. sbase = u32 smem addr of stage.
__device__ __forceinline__ void mma_tile(unsigned sbase, int wm, int wn, int lane,
                                         float acc[4][4][4])
{
    const unsigned aoff0 = (unsigned)((wm * 64 + (lane & 15)) * 80 + (lane >> 4) * 16);
    const unsigned boff0 = (unsigned)((wn * 32 + (lane & 15)) * 80 + (lane >> 4) * 16);
    #pragma unroll
    for (int kk = 0; kk < 2; kk++) {
        unsigned bh[4][2], bl[4][2];
        #pragma unroll
        for (int q = 0; q < 2; q++) {
            unsigned ba = sbase + BHw * 4 + boff0 + q * 1280 + kk * 32;
            ldsm4(bh[2*q][0], bh[2*q+1][0], bh[2*q][1], bh[2*q+1][1], ba);
            ldsm4(bl[2*q][0], bl[2*q+1][0], bl[2*q][1], bl[2*q+1][1], ba + 10240);
        }
        #pragma unroll
        for (int mi = 0; mi < 4; mi++) {
            unsigned aa = sbase + aoff0 + mi * 1280 + kk * 32;
            unsigned ah[4], al[4];
            ldsm4(ah[0], ah[1], ah[2], ah[3], aa);
            ldsm4(al[0], al[1], al[2], al[3], aa + 10240);
            #pragma unroll
            for (int ni = 0; ni < 4; ni++) {
                mma16816(acc[mi][ni], ah, bh[ni]);
                mma16816(acc[mi][ni], ah, bl[ni]);
                mma16816(acc[mi][ni], al, bh[ni]);
            }
        }
    }
}

// ---------------- conv2 (implicit GEMM, fp16 3-pass, ldmatrix, pipelined) ----
__global__ __launch_bounds__(256, 2) void conv2_mma()
{
    extern __shared__ unsigned sm[];
    const unsigned smb = (unsigned)__cvta_generic_to_shared(sm);

    const int tid  = threadIdx.x;
    const int lane = tid & 31;
    const int w    = tid >> 5;
    const int gid  = lane >> 2, tig = lane & 3;
    const int wm   = w >> 2,    wn  = w & 3;

    const int co0 = blockIdx.y * 128;
    const int n0  = blockIdx.x * 128;

    // ---- B gather state ----
    const int bpx  = tid >> 1;
    const int kq   = (tid & 1) * 16;
    const int pixg = n0 + bpx;
    const bool px_ok = (pixg < NPIX);
    int sp_base = 0;
    unsigned vmask = 0;
    if (px_ok) {
        int bimg = pixg / HW;
        int pix  = pixg - bimg * HW;
        int oh = pix / H19, ow = pix - oh * H19;
        sp_base = bimg * HW + pix;
        #pragma unroll
        for (int r = 0; r < 9; r++) {
            int ih = oh + r / 3 - 1, iw = ow + r % 3 - 1;
            if ((unsigned)ih < 19u && (unsigned)iw < 19u) vmask |= 1u << r;
        }
    }
    int cB = kq, rB = 0;

    // ---- A cp.async mapping ----
    const int arow  = tid >> 1;
    const int ahalf = tid & 1;
    const __half* aph = g_w2h + (size_t)(co0 + arow) * C2K + ahalf * 16;
    const __half* apl = g_w2l + (size_t)(co0 + arow) * C2K + ahalf * 16;
    const int adst = arow * SROW + ahalf * 8;
    const int bdst = bpx * SROW + (kq >> 1);

    float acc[4][4][4];
    #pragma unroll
    for (int mi = 0; mi < 4; mi++)
        #pragma unroll
        for (int ni = 0; ni < 4; ni++)
            #pragma unroll
            for (int e = 0; e < 4; e++) acc[mi][ni][e] = 0.f;

    unsigned fv[16];
    auto gatherB = [&](unsigned* dst) {
        bool val = px_ok && ((vmask >> rB) & 1u);
        int dy  = (rB * 11) >> 5;
        int off = dy * H19 + (rB - dy * 3) - 20;
        const unsigned* p = g_xp + (size_t)cB * NPIX + (sp_base + off);
        #pragma unroll
        for (int i = 0; i < 16; i++)
            dst[i] = val ? p[(size_t)i * NPIX] : 0u;
        cB += 32;
        if (cB >= C2IN) { cB -= C2IN; ++rB; }
    };
    auto loadA = [&](unsigned* stage, int it) {
        cp16(stage + AHw + adst,     aph + it * 32);
        cp16(stage + AHw + adst + 4, aph + it * 32 + 8);
        cp16(stage + ALw + adst,     apl + it * 32);
        cp16(stage + ALw + adst + 4, apl + it * 32 + 8);
    };

    loadA(sm, 0);
    cp_commit();
    gatherB(fv);

    const int NIT = C2K / 32;   // 360
    int s = 0;
    for (int it = 0; it < NIT; it++) {
        unsigned* base = sm + s * STG;
        {   // split-store B (hi plane, lo plane), 2x STS.128 each
            unsigned h[8], l[8];
            #pragma unroll
            for (int j = 0; j < 8; j++) {
                h[j] = __byte_perm(fv[2*j], fv[2*j+1], 0x5410);
                l[j] = __byte_perm(fv[2*j], fv[2*j+1], 0x7632);
            }
            uint4* bh = (uint4*)(base + BHw + bdst);
            uint4* bl = (uint4*)(base + BLw + bdst);
            bh[0] = make_uint4(h[0], h[1], h[2], h[3]);
            bh[1] = make_uint4(h[4], h[5], h[6], h[7]);
            bl[0] = make_uint4(l[0], l[1], l[2], l[3]);
            bl[1] = make_uint4(l[4], l[5], l[6], l[7]);
        }
        cp_wait0();
        __syncthreads();

        if (it + 1 < NIT) {
            loadA(sm + (s ^ 1) * STG, it + 1);
            cp_commit();
            gatherB(fv);
        }

        mma_tile(smb + (unsigned)s * (STG * 4), wm, wn, lane, acc);
        s ^= 1;
    }

    // epilogue: BN + leaky -> g_prep pairs [co][gpix]
    #pragma unroll
    for (int mi = 0; mi < 4; mi++) {
        int coA = co0 + wm * 64 + mi * 16 + gid;
        int coB = coA + 8;
        float sA = g_s2[coA], hA = g_h2[coA];
        float sB = g_s2[coB], hB = g_h2[coB];
        #pragma unroll
        for (int ni = 0; ni < 4; ni++) {
            int pg = n0 + wn * 32 + ni * 8 + 2 * tig;
            #pragma unroll
            for (int e = 0; e < 2; e++) {
                int p = pg + e;
                if (p < NPIX) {
                    float y = acc[mi][ni][e] * sA + hA;
                    y = (y > 0.f) ? y : LEAK * y;
                    g_prep[(size_t)coA * NPIX + p] = packpair(y);
                    float z = acc[mi][ni][2 + e] * sB + hB;
                    z = (z > 0.f) ? z : LEAK * z;
                    g_prep[(size_t)coB * NPIX + p] = packpair(z);
                }
            }
        }
    }
}

// ---------------- det head GEMM (fp16 3-pass, ldmatrix, pipelined) ----------
__global__ __launch_bounds__(256, 2) void det_mma(float* __restrict__ out)
{
    extern __shared__ unsigned sm[];
    const unsigned smb = (unsigned)__cvta_generic_to_shared(sm);

    const int tid  = threadIdx.x;
    const int lane = tid & 31;
    const int w    = tid >> 5;
    const int gid  = lane >> 2, tig = lane & 3;
    const int wm   = w >> 2,    wn  = w & 3;

    const int m0 = blockIdx.y * 128;
    const int n0 = blockIdx.x * 128;

    const int bpx  = tid >> 1;
    const int kq   = (tid & 1) * 16;
    const int pixg = n0 + bpx;
    const bool px_ok = (pixg < NPIX);
    const unsigned* pb = g_prep + (size_t)kq * NPIX + (px_ok ? pixg : 0);

    const int arow  = tid >> 1;
    const int ahalf = tid & 1;
    const __half* aph = g_rwh + (size_t)(m0 + arow) * 1024 + ahalf * 16;
    const __half* apl = g_rwl + (size_t)(m0 + arow) * 1024 + ahalf * 16;
    const int adst = arow * SROW + ahalf * 8;
    const int bdst = bpx * SROW + (kq >> 1);

    float acc[4][4][4];
    #pragma unroll
    for (int mi = 0; mi < 4; mi++)
        #pragma unroll
        for (int ni = 0; ni < 4; ni++)
            #pragma unroll
            for (int e = 0; e < 4; e++) acc[mi][ni][e] = 0.f;

    unsigned fv[16];
    auto gatherB = [&](unsigned* dst, int k0) {
        const unsigned* p = pb + (size_t)k0 * NPIX;
        #pragma unroll
        for (int i = 0; i < 16; i++)
            dst[i] = px_ok ? p[(size_t)i * NPIX] : 0u;
    };
    auto loadA = [&](unsigned* stage, int it) {
        cp16(stage + AHw + adst,     aph + it * 32);
        cp16(stage + AHw + adst + 4, aph + it * 32 + 8);
        cp16(stage + ALw + adst,     apl + it * 32);
        cp16(stage + ALw + adst + 4, apl + it * 32 + 8);
    };

    loadA(sm, 0);
    cp_commit();
    gatherB(fv, 0);

    const int NIT = 1024 / 32;   // 32
    int s = 0;
    for (int it = 0; it < NIT; it++) {
        unsigned* base = sm + s * STG;
        {
            unsigned h[8], l[8];
            #pragma unroll
            for (int j = 0; j < 8; j++) {
                h[j] = __byte_perm(fv[2*j], fv[2*j+1], 0x5410);
                l[j] = __byte_perm(fv[2*j], fv[2*j+1], 0x7632);
            }
            uint4* bh = (uint4*)(base + BHw + bdst);
            uint4* bl = (uint4*)(base + BLw + bdst);
            bh[0] = make_uint4(h[0], h[1], h[2], h[3]);
            bh[1] = make_uint4(h[4], h[5], h[6], h[7]);
            bl[0] = make_uint4(l[0], l[1], l[2], l[3]);
            bl[1] = make_uint4(l[4], l[5], l[6], l[7]);
        }
        cp_wait0();
        __syncthreads();

        if (it + 1 < NIT) {
            loadA(sm + (s ^ 1) * STG, it + 1);
            cp_commit();
            gatherB(fv, (it + 1) * 32);
        }

        mma_tile(smb + (unsigned)s * (STG * 4), wm, wn, lane, acc);
        s ^= 1;
    }

    #pragma unroll
    for (int mi = 0; mi < 4; mi++) {
        int mA = m0 + wm * 64 + mi * 16 + gid;
        int mB = mA + 8;
        float cA = (mA < KO) ? g_cb[mA] : 0.f;
        float cB2 = (mB < KO) ? g_cb[mB] : 0.f;
        #pragma unroll
        for (int ni = 0; ni < 4; ni++) {
            int pg = n0 + wn * 32 + ni * 8 + 2 * tig;
            #pragma unroll
            for (int e = 0; e < 2; e++) {
                int p = pg + e;
                if (p < NPIX) {
                    int b = p / HW, pp = p - b * HW;
                    if (mA < KO)
                        out[((size_t)b * KO + mA) * HW + pp] = acc[mi][ni][e] + cA;
                    if (mB < KO)
                        out[((size_t)b * KO + mB) * HW + pp] = acc[mi][ni][2 + e] + cB2;
                }
            }
        }
    }
}

// ---------------- launch ----------------------------------------------------
extern "C" void kernel_launch(void* const* d_in, const int* in_sizes, int n_in,
                              void* d_out, int out_size)
{
    const float* feat0 = (const float*)d_in[0];
    const float* feat1 = (const float*)d_in[1];
    const float* w1    = (const float*)d_in[2];
    const float* g1    = (const float*)d_in[3];
    const float* b1    = (const float*)d_in[4];
    const float* m1    = (const float*)d_in[5];
    const float* v1    = (const float*)d_in[6];
    const float* w2    = (const float*)d_in[7];
    const float* g2    = (const float*)d_in[8];
    const float* b2    = (const float*)d_in[9];
    const float* m2    = (const float*)d_in[10];
    const float* v2    = (const float*)d_in[11];
    const float* rw    = (const float*)d_in[12];
    float* out = (float*)d_out;

    cudaFuncSetAttribute(conv2_mma, cudaFuncAttributeMaxDynamicSharedMemorySize, SMEMB);
    cudaFuncSetAttribute(det_mma,   cudaFuncAttributeMaxDynamicSharedMemorySize, SMEMB);

    prep_kernel<<<46080, 256>>>(w1, g1, b1, m1, v1, g2, b2, m2, v2, rw, w2);
    feat0_split<<<92416, 256>>>(feat0);
    conv1_kernel<<<dim3(91, NB), 256>>>(feat1);
    conv2_mma<<<dim3(181, 8), 256, SMEMB>>>();
    det_mma  <<<dim3(181, 5), 256, SMEMB>>>(out);
}

// round 10
// speedup vs baseline: 1.1565x; 1.1565x over previous
#include <cuda_runtime.h>
#include <cuda_fp16.h>

#define LEAK  0.1f
#define BNEPS 1e-5f

#define NB    64
#define HW    361            // 19*19
#define H19   19
#define C2IN  1280
#define C2K   11520          // 1280*9
#define KO    600
#define KOP   640
#define NPIX  (NB * HW)      // 23104

#define SROW  20             // smem row stride in u32 (80 B)
#define AH0w  0              // word offsets: A k' chunk0 (orig k 0..15)
#define AH1w  2560           // A chunk1 (orig k 16..31)
#define BH0w  5120
#define BH1w  7680
#define STG   10240          // u32 per stage
#define STGB  40960u         // bytes per stage
#define SMEMB (2 * STG * 4)  // 81920 bytes

// ---------------- device scratch ----------------
__device__ float g_w1t[512 * 64];
__device__ float g_s1[64],  g_h1[64];
__device__ float g_s2[1024], g_h2[1024];
__device__ float g_cb[KO];
__device__ unsigned g_xp  [(size_t)C2IN * NPIX];   // conv2 input (h|l<<16) fp16 pairs [c][gpix]
__device__ unsigned g_prep[(size_t)1024 * NPIX];   // det input pairs [c][gpix]
__device__ __align__(16) unsigned g_w2p[(size_t)1024 * C2K];  // w2 pairs, K-order r*1280+c
__device__ __align__(16) unsigned g_rwp[(size_t)KOP * 1024];  // reweight pairs

__device__ __forceinline__ unsigned packpair(float x)
{
    __half h = __float2half_rn(x);
    float r = x - __half2float(h);
    __half l = __float2half_rn(r);
    return ((unsigned)__half_as_ushort(l) << 16) | (unsigned)__half_as_ushort(h);
}

// ---------------- cp.async helpers ----------------
__device__ __forceinline__ void cp16(void* smem, const void* g)
{
    unsigned sa = (unsigned)__cvta_generic_to_shared(smem);
    asm volatile("cp.async.cg.shared.global [%0], [%1], 16;\n" :: "r"(sa), "l"(g));
}
// 4-byte cp.async with zero-fill when n==0 (n in {0,4})
__device__ __forceinline__ void cp4z(void* smem, const void* g, unsigned n)
{
    unsigned sa = (unsigned)__cvta_generic_to_shared(smem);
    asm volatile("cp.async.ca.shared.global [%0], [%1], 4, %2;\n"
                 :: "r"(sa), "l"(g), "r"(n));
}
__device__ __forceinline__ void cp_commit() { asm volatile("cp.async.commit_group;\n"); }
__device__ __forceinline__ void cp_wait0()  { asm volatile("cp.async.wait_group 0;\n"); }

// ---------------- prep ----------------
__global__ void prep_kernel(const float* __restrict__ w1,
                            const float* __restrict__ g1, const float* __restrict__ b1,
                            const float* __restrict__ m1, const float* __restrict__ v1,
                            const float* __restrict__ g2, const float* __restrict__ b2,
                            const float* __restrict__ m2, const float* __restrict__ v2,
                            const float* __restrict__ rw, const float* __restrict__ w2)
{
    long long i = (long long)blockIdx.x * blockDim.x + threadIdx.x;
    if (i < (long long)1024 * C2K) {
        int co = (int)(i / C2K);
        int t  = (int)(i - (long long)co * C2K);
        int r  = t / C2IN;
        int c  = t - r * C2IN;
        g_w2p[i] = packpair(w2[(size_t)co * C2K + c * 9 + r]);
    }
    if (i < (long long)KOP * 1024) {
        int m = (int)(i >> 10), c = (int)(i & 1023);
        g_rwp[i] = packpair((m < KO) ? rw[m * 1025 + c] : 0.f);
    }
    if (i < 512 * 64) {
        int k = (int)(i >> 6), co = (int)(i & 63);
        g_w1t[i] = w1[co * 512 + k];
    }
    if (i < KO)   g_cb[i] = rw[i * 1025 + 1024];
    if (i < 64)   { float s = g1[i] * rsqrtf(v1[i] + BNEPS); g_s1[i] = s; g_h1[i] = b1[i] - m1[i] * s; }
    if (i < 1024) { float s = g2[i] * rsqrtf(v2[i] + BNEPS); g_s2[i] = s; g_h2[i] = b2[i] - m2[i] * s; }
}

__global__ void feat0_split(const float* __restrict__ feat0)
{
    long long i = (long long)blockIdx.x * blockDim.x + threadIdx.x;
    if (i < (long long)NB * 1024 * HW) {
        int hw = (int)(i % HW);
        long long t = i / HW;
        int c = (int)(t & 1023);
        int b = (int)(t >> 10);
        g_xp[(size_t)(256 + c) * NPIX + b * HW + hw] = packpair(feat0[i]);
    }
}

// ---------------- conv1 (unchanged) ----------------
__global__ __launch_bounds__(256) void conv1_kernel(const float* __restrict__ feat1)
{
    __shared__ __align__(16) float s_in[512][16];
    __shared__ float s_w[64][64];

    const int b    = blockIdx.y;
    const int base = blockIdx.x * 16;
    const float* f = feat1 + (size_t)b * 512 * 1444;

    for (int idx = threadIdx.x; idx < 512 * 16; idx += 256) {
        int p = idx & 15, k = idx >> 4;
        int pix = base + p;
        s_in[k][p] = (pix < 1444) ? f[k * 1444 + pix] : 0.f;
    }

    const int co = threadIdx.x & 63;
    const int pq = threadIdx.x >> 6;
    float acc[4] = {0.f, 0.f, 0.f, 0.f};

    for (int kc = 0; kc < 512; kc += 64) {
        __syncthreads();
        for (int idx = threadIdx.x; idx < 64 * 64; idx += 256)
            s_w[idx >> 6][idx & 63] = g_w1t[(kc + (idx >> 6)) * 64 + (idx & 63)];
        __syncthreads();
        #pragma unroll
        for (int kk = 0; kk < 64; kk++) {
            float  w = s_w[kk][co];
            float4 v = *(const float4*)&s_in[kc + kk][pq * 4];
            acc[0] += v.x * w; acc[1] += v.y * w;
            acc[2] += v.z * w; acc[3] += v.w * w;
        }
    }

    const float s = g_s1[co], hh = g_h1[co];
    #pragma unroll
    for (int j = 0; j < 4; j++) {
        int pix = base + pq * 4 + j;
        if (pix < 1444) {
            float y = acc[j] * s + hh;
            y = (y > 0.f) ? y : LEAK * y;
            int h38 = pix / 38, w38 = pix - h38 * 38;
            int cc  = ((h38 & 1) * 2 + (w38 & 1)) * 64 + co;
            int gp  = b * HW + (h38 >> 1) * H19 + (w38 >> 1);
            g_xp[(size_t)cc * NPIX + gp] = packpair(y);
        }
    }
}

// ---------------- mma / ldmatrix helpers ----------------
__device__ __forceinline__ void mma16816(float* d, const unsigned* a, const unsigned* b)
{
    asm volatile(
        "mma.sync.aligned.m16n8k16.row.col.f32.f16.f16.f32 "
        "{%0,%1,%2,%3},{%4,%5,%6,%7},{%8,%9},{%0,%1,%2,%3};"
        : "+f"(d[0]), "+f"(d[1]), "+f"(d[2]), "+f"(d[3])
        : "r"(a[0]), "r"(a[1]), "r"(a[2]), "r"(a[3]), "r"(b[0]), "r"(b[1]));
}

__device__ __forceinline__ void ldsm4(unsigned& r0, unsigned& r1, unsigned& r2, unsigned& r3,
                                      unsigned saddr)
{
    asm volatile("ldmatrix.sync.aligned.m8n8.x4.shared.b16 {%0,%1,%2,%3}, [%4];"
                 : "=r"(r0), "=r"(r1), "=r"(r2), "=r"(r3) : "r"(saddr));
}

// diagonal K'-interleaved scheme: 2 k'-chunks x 2 K16 x (4m x 4n) = 64 MMAs.
// sb = byte smem addr of stage; aoff/boff = per-thread ldmatrix offsets.
__device__ __forceinline__ void mma_tile(unsigned sb, unsigned aoff, unsigned boff,
                                         float acc[4][4][4])
{
    #pragma unroll
    for (int ch = 0; ch < 2; ch++) {
        const unsigned abase = sb + (ch ? (AH1w * 4u) : 0u) + aoff;
        const unsigned bbase = sb + (ch ? (BH1w * 4u) : (BH0w * 4u)) + boff;
        #pragma unroll
        for (int kk = 0; kk < 2; kk++) {
            unsigned b[4][2];
            #pragma unroll
            for (int q = 0; q < 2; q++)
                ldsm4(b[2*q][0], b[2*q+1][0], b[2*q][1], b[2*q+1][1],
                      bbase + q * 1280u + kk * 32u);
            #pragma unroll
            for (int mi = 0; mi < 4; mi++) {
                unsigned a[4];
                ldsm4(a[0], a[1], a[2], a[3], abase + mi * 1280u + kk * 32u);
                #pragma unroll
                for (int ni = 0; ni < 4; ni++)
                    mma16816(acc[mi][ni], a, b[ni]);
            }
        }
    }
}

// ---------------- conv2 (diagonal fp16, ldmatrix + cp.async B) ---------------
__global__ __launch_bounds__(256, 2) void conv2_mma()
{
    extern __shared__ unsigned sm[];
    const unsigned smb = (unsigned)__cvta_generic_to_shared(sm);

    const int tid  = threadIdx.x;
    const int lane = tid & 31;
    const int w    = tid >> 5;
    const int gid  = lane >> 2, tig = lane & 3;
    const int wm   = w >> 2,    wn  = w & 3;

    const int co0 = blockIdx.y * 128;
    const int n0  = blockIdx.x * 128;

    // ---- B gather state ----
    const int bpx  = tid >> 1;
    const int kq   = (tid & 1) * 16;
    const int pixg = n0 + bpx;
    const bool px_ok = (pixg < NPIX);
    int sp_base = 0;
    unsigned vmask = 0;
    if (px_ok) {
        int bimg = pixg / HW;
        int pix  = pixg - bimg * HW;
        int oh = pix / H19, ow = pix - oh * H19;
        sp_base = bimg * HW + pix;
        #pragma unroll
        for (int r = 0; r < 9; r++) {
            int ih = oh + r / 3 - 1, iw = ow + r % 3 - 1;
            if ((unsigned)ih < 19u && (unsigned)iw < 19u) vmask |= 1u << r;
        }
    }
    int cB = kq, rB = 0;

    // ---- A cp.async mapping ----
    const int arow  = tid >> 1;
    const int ahalf = tid & 1;
    const unsigned* ap = g_w2p + (size_t)(co0 + arow) * C2K + ahalf * 8;
    const int adst = arow * SROW + ahalf * 8;
    const int bdst = (kq ? BH1w : BH0w) + bpx * SROW;

    // ldmatrix per-thread offsets (bytes)
    const unsigned aoff = (unsigned)((wm * 64 + (lane & 15)) * 80 + (lane >> 4) * 16);
    const unsigned boff = (unsigned)((wn * 32 + (lane & 15)) * 80 + (lane >> 4) * 16);

    float acc[4][4][4];
    #pragma unroll
    for (int mi = 0; mi < 4; mi++)
        #pragma unroll
        for (int ni = 0; ni < 4; ni++)
            #pragma unroll
            for (int e = 0; e < 4; e++) acc[mi][ni][e] = 0.f;

    auto loadA = [&](unsigned* stage, int it) {
        const unsigned* src = ap + it * 32;
        cp16(stage + AH0w + adst,     src);
        cp16(stage + AH0w + adst + 4, src + 4);
        cp16(stage + AH1w + adst,     src + 16);
        cp16(stage + AH1w + adst + 4, src + 20);
    };
    auto loadB = [&](unsigned* stage) {
        bool val = px_ok && ((vmask >> rB) & 1u);
        int dy  = (rB * 11) >> 5;
        int off = dy * H19 + (rB - dy * 3) - 20;
        const unsigned* p = g_xp + (size_t)cB * NPIX + (sp_base + off);
        unsigned n = val ? 4u : 0u;
        unsigned* dst = stage + bdst;
        #pragma unroll
        for (int i = 0; i < 16; i++)
            cp4z(dst + i, p + (size_t)i * NPIX, n);
        cB += 32;
        if (cB >= C2IN) { cB -= C2IN; ++rB; }
    };

    // prologue: stage 0 loads for it=0
    loadA(sm, 0);
    loadB(sm);
    cp_commit();

    const int NIT = C2K / 32;   // 360 (even)
    for (int it = 0; it < NIT; it += 2) {
        cp_wait0();
        __syncthreads();
        // it+1 -> stage 1 (NIT even => it+1 < NIT always here)
        loadA(sm + STG, it + 1);
        loadB(sm + STG);
        cp_commit();
        mma_tile(smb, aoff, boff, acc);

        cp_wait0();
        __syncthreads();
        if (it + 2 < NIT) {
            loadA(sm, it + 2);
            loadB(sm);
            cp_commit();
        }
        mma_tile(smb + STGB, aoff, boff, acc);
    }

    // epilogue: BN + leaky -> g_prep pairs [co][gpix]
    #pragma unroll
    for (int mi = 0; mi < 4; mi++) {
        int coA = co0 + wm * 64 + mi * 16 + gid;
        int coB = coA + 8;
        float sA = g_s2[coA], hA = g_h2[coA];
        float sB = g_s2[coB], hB = g_h2[coB];
        #pragma unroll
        for (int ni = 0; ni < 4; ni++) {
            int pg = n0 + wn * 32 + ni * 8 + 2 * tig;
            #pragma unroll
            for (int e = 0; e < 2; e++) {
                int p = pg + e;
                if (p < NPIX) {
                    float y = acc[mi][ni][e] * sA + hA;
                    y = (y > 0.f) ? y : LEAK * y;
                    g_prep[(size_t)coA * NPIX + p] = packpair(y);
                    float z = acc[mi][ni][2 + e] * sB + hB;
                    z = (z > 0.f) ? z : LEAK * z;
                    g_prep[(size_t)coB * NPIX + p] = packpair(z);
                }
            }
        }
    }
}

// ---------------- det head GEMM (same scheme) ---------------------------------
__global__ __launch_bounds__(256, 2) void det_mma(float* __restrict__ out)
{
    extern __shared__ unsigned sm[];
    const unsigned smb = (unsigned)__cvta_generic_to_shared(sm);

    const int tid  = threadIdx.x;
    const int lane = tid & 31;
    const int w    = tid >> 5;
    const int gid  = lane >> 2, tig = lane & 3;
    const int wm   = w >> 2,    wn  = w & 3;

    const int m0 = blockIdx.y * 128;
    const int n0 = blockIdx.x * 128;

    const int bpx  = tid >> 1;
    const int kq   = (tid & 1) * 16;
    const int pixg = n0 + bpx;
    const bool px_ok = (pixg < NPIX);
    const unsigned* pb = g_prep + (size_t)kq * NPIX + (px_ok ? pixg : 0);
    const unsigned nsz = px_ok ? 4u : 0u;

    const int arow  = tid >> 1;
    const int ahalf = tid & 1;
    const unsigned* ap = g_rwp + (size_t)(m0 + arow) * 1024 + ahalf * 8;
    const int adst = arow * SROW + ahalf * 8;
    const int bdst = (kq ? BH1w : BH0w) + bpx * SROW;

    const unsigned aoff = (unsigned)((wm * 64 + (lane & 15)) * 80 + (lane >> 4) * 16);
    const unsigned boff = (unsigned)((wn * 32 + (lane & 15)) * 80 + (lane >> 4) * 16);

    float acc[4][4][4];
    #pragma unroll
    for (int mi = 0; mi < 4; mi++)
        #pragma unroll
        for (int ni = 0; ni < 4; ni++)
            #pragma unroll
            for (int e = 0; e < 4; e++) acc[mi][ni][e] = 0.f;

    auto loadA = [&](unsigned* stage, int it) {
        const unsigned* src = ap + it * 32;
        cp16(stage + AH0w + adst,     src);
        cp16(stage + AH0w + adst + 4, src + 4);
        cp16(stage + AH1w + adst,     src + 16);
        cp16(stage + AH1w + adst + 4, src + 20);
    };
    auto loadB = [&](unsigned* stage, int it) {
        const unsigned* p = pb + (size_t)(it * 32) * NPIX;
        unsigned* dst = stage + bdst;
        #pragma unroll
        for (int i = 0; i < 16; i++)
            cp4z(dst + i, p + (size_t)i * NPIX, nsz);
    };

    loadA(sm, 0);
    loadB(sm, 0);
    cp_commit();

    const int NIT = 1024 / 32;   // 32 (even)
    for (int it = 0; it < NIT; it += 2) {
        cp_wait0();
        __syncthreads();
        loadA(sm + STG, it + 1);
        loadB(sm + STG, it + 1);
        cp_commit();
        mma_tile(smb, aoff, boff, acc);

        cp_wait0();
        __syncthreads();
        if (it + 2 < NIT) {
            loadA(sm, it + 2);
            loadB(sm, it + 2);
            cp_commit();
        }
        mma_tile(smb + STGB, aoff, boff, acc);
    }

    #pragma unroll
    for (int mi = 0; mi < 4; mi++) {
        int mA = m0 + wm * 64 + mi * 16 + gid;
        int mB = mA + 8;
        float cA = (mA < KO) ? g_cb[mA] : 0.f;
        float cB2 = (mB < KO) ? g_cb[mB] : 0.f;
        #pragma unroll
        for (int ni = 0; ni < 4; ni++) {
            int pg = n0 + wn * 32 + ni * 8 + 2 * tig;
            #pragma unroll
            for (int e = 0; e < 2; e++) {
                int p = pg + e;
                if (p < NPIX) {
                    int b = p / HW, pp = p - b * HW;
                    if (mA < KO)
                        out[((size_t)b * KO + mA) * HW + pp] = acc[mi][ni][e] + cA;
                    if (mB < KO)
                        out[((size_t)b * KO + mB) * HW + pp] = acc[mi][ni][2 + e] + cB2;
                }
            }
        }
    }
}

// ---------------- launch ----------------------------------------------------
extern "C" void kernel_launch(void* const* d_in, const int* in_sizes, int n_in,
                              void* d_out, int out_size)
{
    const float* feat0 = (const float*)d_in[0];
    const float* feat1 = (const float*)d_in[1];
    const float* w1    = (const float*)d_in[2];
    const float* g1    = (const float*)d_in[3];
    const float* b1    = (const float*)d_in[4];
    const float* m1    = (const float*)d_in[5];
    const float* v1    = (const float*)d_in[6];
    const float* w2    = (const float*)d_in[7];
    const float* g2    = (const float*)d_in[8];
    const float* b2    = (const float*)d_in[9];
    const float* m2    = (const float*)d_in[10];
    const float* v2    = (const float*)d_in[11];
    const float* rw    = (const float*)d_in[12];
    float* out = (float*)d_out;

    cudaFuncSetAttribute(conv2_mma, cudaFuncAttributeMaxDynamicSharedMemorySize, SMEMB);
    cudaFuncSetAttribute(det_mma,   cudaFuncAttributeMaxDynamicSharedMemorySize, SMEMB);

    prep_kernel<<<46080, 256>>>(w1, g1, b1, m1, v1, g2, b2, m2, v2, rw, w2);
    feat0_split<<<92416, 256>>>(feat0);
    conv1_kernel<<<dim3(91, NB), 256>>>(feat1);
    conv2_mma<<<dim3(181, 8), 256, SMEMB>>>();
    det_mma  <<<dim3(181, 5), 256, SMEMB>>>(out);
}

// round 11
// speedup vs baseline: 2.2435x; 1.9400x over previous
#include <cuda_runtime.h>
#include <cuda_fp16.h>

#define LEAK  0.1f
#define BNEPS 1e-5f

#define NB    64
#define HW    361            // 19*19
#define H19   19
#define C2IN  1280
#define C2K   11520          // 1280*9 (fp16 K total)
#define KWORD 5760           // C2K/2 u32 words per weight row
#define KO    600
#define KOP   640
#define NPIX  (NB * HW)      // 23104

#define SROW  20             // smem row stride in u32 (80 B)
#define AH0w  0              // A k-words 0..15 of iter (fp16 k 0..31)
#define AH1w  2560           // A k-words 16..31 (fp16 k 32..63)
#define BH0w  5120
#define BH1w  7680
#define STG   10240          // u32 per stage
#define SMEMB (2 * STG * 4)  // 81920 bytes

// ---------------- device scratch ----------------
__device__ float g_w1t[512 * 64];
__device__ float g_s1[64],  g_h1[64];
__device__ float g_s2[1024], g_h2[1024];
__device__ float g_cb[KO];
__device__ unsigned g_xh2[(size_t)(C2IN / 2) * NPIX];  // conv2 input, ch-paired fp16 [c/2][gpix]
__device__ unsigned g_ps2[(size_t)512 * NPIX];         // det input, ch-paired fp16 [c/2][gpix]
__device__ __align__(16) unsigned g_w2s[(size_t)1024 * KWORD]; // w2 fp16 pairs, K-order r*1280+c
__device__ __align__(16) unsigned g_rws[(size_t)KOP * 512];    // reweight fp16 pairs

__device__ __forceinline__ unsigned pack2(float lo, float hi)
{
    __half2 h = __floats2half2_rn(lo, hi);
    return *reinterpret_cast<unsigned*>(&h);
}

// ---------------- cp.async helpers ----------------
__device__ __forceinline__ void cp16(void* smem, const void* g)
{
    unsigned sa = (unsigned)__cvta_generic_to_shared(smem);
    asm volatile("cp.async.cg.shared.global [%0], [%1], 16;\n" :: "r"(sa), "l"(g));
}
__device__ __forceinline__ void cp_commit() { asm volatile("cp.async.commit_group;\n"); }
__device__ __forceinline__ void cp_wait0()  { asm volatile("cp.async.wait_group 0;\n"); }

// ---------------- prep: BN fold, fp16 pair packing --------------------------
__global__ void prep_kernel(const float* __restrict__ w1,
                            const float* __restrict__ g1, const float* __restrict__ b1,
                            const float* __restrict__ m1, const float* __restrict__ v1,
                            const float* __restrict__ g2, const float* __restrict__ b2,
                            const float* __restrict__ m2, const float* __restrict__ v2,
                            const float* __restrict__ rw, const float* __restrict__ w2)
{
    long long i = (long long)blockIdx.x * blockDim.x + threadIdx.x;
    if (i < (long long)1024 * KWORD) {
        // dest word: row co, word j -> fp16 k-pair (2j, 2j+1); k = r*1280 + c
        int co = (int)(i / KWORD);
        int j  = (int)(i - (long long)co * KWORD);
        int r  = j / 640;                    // 640 words per tap
        int c  = (j - r * 640) * 2;
        float x0 = w2[(size_t)co * C2K + c * 9 + r];
        float x1 = w2[(size_t)co * C2K + (c + 1) * 9 + r];
        g_w2s[i] = pack2(x0, x1);
    }
    if (i < (long long)KOP * 512) {
        int m = (int)(i >> 9), j = (int)(i & 511);
        float x0 = (m < KO) ? rw[m * 1025 + 2 * j]     : 0.f;
        float x1 = (m < KO) ? rw[m * 1025 + 2 * j + 1] : 0.f;
        g_rws[i] = pack2(x0, x1);
    }
    if (i < 512 * 64) {
        int k = (int)(i >> 6), co = (int)(i & 63);
        g_w1t[i] = w1[co * 512 + k];
    }
    if (i < KO)   g_cb[i] = rw[i * 1025 + 1024];
    if (i < 64)   { float s = g1[i] * rsqrtf(v1[i] + BNEPS); g_s1[i] = s; g_h1[i] = b1[i] - m1[i] * s; }
    if (i < 1024) { float s = g2[i] * rsqrtf(v2[i] + BNEPS); g_s2[i] = s; g_h2[i] = b2[i] - m2[i] * s; }
}

// ---------------- feat0 -> g_xh2 channel-pairs 128..639 ----------------
__global__ void feat0_split(const float* __restrict__ feat0)
{
    long long i = (long long)blockIdx.x * blockDim.x + threadIdx.x;
    if (i < (long long)NB * 512 * HW) {
        int hw = (int)(i % HW);
        long long t = i / HW;
        int cp = (int)(t & 511);
        int b  = (int)(t >> 9);
        const float* src = feat0 + ((size_t)b * 1024 + 2 * cp) * HW + hw;
        g_xh2[(size_t)(128 + cp) * NPIX + b * HW + hw] = pack2(src[0], src[HW]);
    }
}

// ---------------- conv1 (1x1, 512->64) + BN + leaky + reorg(2) --------------
__global__ __launch_bounds__(256) void conv1_kernel(const float* __restrict__ feat1)
{
    __shared__ __align__(16) float s_in[512][16];
    __shared__ float s_w[64][64];

    const int b    = blockIdx.y;
    const int base = blockIdx.x * 16;
    const float* f = feat1 + (size_t)b * 512 * 1444;

    for (int idx = threadIdx.x; idx < 512 * 16; idx += 256) {
        int p = idx & 15, k = idx >> 4;
        int pix = base + p;
        s_in[k][p] = (pix < 1444) ? f[k * 1444 + pix] : 0.f;
    }

    const int co = threadIdx.x & 63;
    const int pq = threadIdx.x >> 6;
    float acc[4] = {0.f, 0.f, 0.f, 0.f};

    for (int kc = 0; kc < 512; kc += 64) {
        __syncthreads();
        for (int idx = threadIdx.x; idx < 64 * 64; idx += 256)
            s_w[idx >> 6][idx & 63] = g_w1t[(kc + (idx >> 6)) * 64 + (idx & 63)];
        __syncthreads();
        #pragma unroll
        for (int kk = 0; kk < 64; kk++) {
            float  w = s_w[kk][co];
            float4 v = *(const float4*)&s_in[kc + kk][pq * 4];
            acc[0] += v.x * w; acc[1] += v.y * w;
            acc[2] += v.z * w; acc[3] += v.w * w;
        }
    }

    const float s = g_s1[co], hh = g_h1[co];
    #pragma unroll
    for (int j = 0; j < 4; j++) {
        int pix = base + pq * 4 + j;
        float y = acc[j] * s + hh;
        y = (y > 0.f) ? y : LEAK * y;
        float y2 = __shfl_down_sync(0xffffffffu, y, 1);   // co+1's value (same warp)
        if (!(co & 1) && pix < 1444) {
            int h38 = pix / 38, w38 = pix - h38 * 38;
            int cc  = ((h38 & 1) * 2 + (w38 & 1)) * 64 + co;   // even
            int gp  = b * HW + (h38 >> 1) * H19 + (w38 >> 1);
            g_xh2[(size_t)(cc >> 1) * NPIX + gp] = pack2(y, y2);
        }
    }
}

// ---------------- mma.sync helper (fp16, fp32 accum) -------------------------
__device__ __forceinline__ void mma16816(float* d, const unsigned* a, const unsigned* b)
{
    asm volatile(
        "mma.sync.aligned.m16n8k16.row.col.f32.f16.f16.f32 "
        "{%0,%1,%2,%3},{%4,%5,%6,%7},{%8,%9},{%0,%1,%2,%3};"
        : "+f"(d[0]), "+f"(d[1]), "+f"(d[2]), "+f"(d[3])
        : "r"(a[0]), "r"(a[1]), "r"(a[2]), "r"(a[3]), "r"(b[0]), "r"(b[1]));
}

// plain fp16 GEMM over K=64 per stage (two 16-word chunks x 2 K16) = 64 MMAs
__device__ __forceinline__ void mma_tile(const unsigned* A0, const unsigned* A1,
                                         const unsigned* B0, const unsigned* B1,
                                         int wm, int wn, int gid, int tig,
                                         float acc[4][4][4])
{
    #pragma unroll
    for (int ch = 0; ch < 2; ch++) {
        const unsigned* Ac = ch ? A1 : A0;
        const unsigned* Bc = ch ? B1 : B0;
        #pragma unroll
        for (int kk = 0; kk < 2; kk++) {
            const int koff = kk * 8;
            unsigned b[4][2];
            #pragma unroll
            for (int ni = 0; ni < 4; ni++) {
                int col = (wn * 32 + ni * 8 + gid) * SROW + koff + tig;
                b[ni][0] = Bc[col]; b[ni][1] = Bc[col + 4];
            }
            #pragma unroll
            for (int mi = 0; mi < 4; mi++) {
                int r0 = (wm * 64 + mi * 16 + gid) * SROW + koff + tig;
                int r1 = r0 + 8 * SROW;
                unsigned a[4] = {Ac[r0], Ac[r1], Ac[r0 + 4], Ac[r1 + 4]};
                #pragma unroll
                for (int ni = 0; ni < 4; ni++)
                    mma16816(acc[mi][ni], a, b[ni]);
            }
        }
    }
}

// ---------------- conv2 (implicit GEMM, plain fp16, K64/iter, pipelined) ----
__global__ __launch_bounds__(256, 2) void conv2_mma()
{
    extern __shared__ unsigned sm[];

    const int tid  = threadIdx.x;
    const int lane = tid & 31;
    const int w    = tid >> 5;
    const int gid  = lane >> 2, tig = lane & 3;
    const int wm   = w >> 2,    wn  = w & 3;

    const int co0 = blockIdx.y * 128;
    const int n0  = blockIdx.x * 128;

    // ---- B gather state ----
    const int bpx  = tid >> 1;
    const int kq   = (tid & 1) * 16;    // word offset within iter's 32 words
    const int pixg = n0 + bpx;
    const bool px_ok = (pixg < NPIX);
    int sp_base = 0;
    unsigned vmask = 0;
    if (px_ok) {
        int bimg = pixg / HW;
        int pix  = pixg - bimg * HW;
        int oh = pix / H19, ow = pix - oh * H19;
        sp_base = bimg * HW + pix;
        #pragma unroll
        for (int r = 0; r < 9; r++) {
            int ih = oh + r / 3 - 1, iw = ow + r % 3 - 1;
            if ((unsigned)ih < 19u && (unsigned)iw < 19u) vmask |= 1u << r;
        }
    }
    int wb = kq, rB = 0;                // word-in-tap (640 words per tap), tap index

    // ---- A cp.async mapping: 32 words/row/iter, 2 threads/row ----
    const int arow  = tid >> 1;
    const int ahalf = tid & 1;
    const unsigned* ap = g_w2s + (size_t)(co0 + arow) * KWORD + ahalf * 8;
    const int adst = arow * SROW + ahalf * 8;
    const int bdst = (kq ? BH1w : BH0w) + bpx * SROW;

    float acc[4][4][4];
    #pragma unroll
    for (int mi = 0; mi < 4; mi++)
        #pragma unroll
        for (int ni = 0; ni < 4; ni++)
            #pragma unroll
            for (int e = 0; e < 4; e++) acc[mi][ni][e] = 0.f;

    unsigned fv[16];
    auto gatherB = [&](unsigned* dst) {
        bool val = px_ok && ((vmask >> rB) & 1u);
        int dy  = (rB * 11) >> 5;
        int off = dy * H19 + (rB - dy * 3) - 20;
        const unsigned* p = g_xh2 + (size_t)wb * NPIX + (sp_base + off);
        #pragma unroll
        for (int i = 0; i < 16; i++)
            dst[i] = val ? p[(size_t)i * NPIX] : 0u;
        wb += 32;
        if (wb >= 640) { wb -= 640; ++rB; }
    };
    auto loadA = [&](unsigned* stage, int it) {
        const unsigned* src = ap + it * 32;
        cp16(stage + AH0w + adst,     src);
        cp16(stage + AH0w + adst + 4, src + 4);
        cp16(stage + AH1w + adst,     src + 16);
        cp16(stage + AH1w + adst + 4, src + 20);
    };

    loadA(sm, 0);
    cp_commit();
    gatherB(fv);

    const int NIT = KWORD / 32;   // 180
    int s = 0;
    for (int it = 0; it < NIT; it++) {
        unsigned* base = sm + s * STG;
        {   // B regs -> stage (4x STS.128, words already k-paired)
            uint4* bd = (uint4*)(base + bdst);
            bd[0] = make_uint4(fv[0],  fv[1],  fv[2],  fv[3]);
            bd[1] = make_uint4(fv[4],  fv[5],  fv[6],  fv[7]);
            bd[2] = make_uint4(fv[8],  fv[9],  fv[10], fv[11]);
            bd[3] = make_uint4(fv[12], fv[13], fv[14], fv[15]);
        }
        cp_wait0();
        __syncthreads();

        if (it + 1 < NIT) {
            loadA(sm + (s ^ 1) * STG, it + 1);
            cp_commit();
            gatherB(fv);    // overlaps MMAs below
        }

        mma_tile(base + AH0w, base + AH1w, base + BH0w, base + BH1w,
                 wm, wn, gid, tig, acc);
        s ^= 1;
    }

    // epilogue: BN + leaky -> g_ps2 channel-paired fp16
    #pragma unroll
    for (int mi = 0; mi < 4; mi++) {
        int coA = co0 + wm * 64 + mi * 16 + gid;
        int coB = coA + 8;
        float sA = g_s2[coA], hA = g_h2[coA];
        float sB = g_s2[coB], hB = g_h2[coB];
        #pragma unroll
        for (int ni = 0; ni < 4; ni++) {
            int pg = n0 + wn * 32 + ni * 8 + 2 * tig;
            #pragma unroll
            for (int e = 0; e < 2; e++) {
                int p = pg + e;
                float y = acc[mi][ni][e] * sA + hA;
                y = (y > 0.f) ? y : LEAK * y;
                float z = acc[mi][ni][2 + e] * sB + hB;
                z = (z > 0.f) ? z : LEAK * z;
                float y2 = __shfl_down_sync(0xffffffffu, y, 4);  // gid+1 -> co+1
                float z2 = __shfl_down_sync(0xffffffffu, z, 4);
                if (!(gid & 1) && p < NPIX) {
                    g_ps2[(size_t)(coA >> 1) * NPIX + p] = pack2(y, y2);
                    g_ps2[(size_t)(coB >> 1) * NPIX + p] = pack2(z, z2);
                }
            }
        }
    }
}

// ---------------- det head GEMM (plain fp16, K64/iter) -----------------------
__global__ __launch_bounds__(256, 2) void det_mma(float* __restrict__ out)
{
    extern __shared__ unsigned sm[];

    const int tid  = threadIdx.x;
    const int lane = tid & 31;
    const int w    = tid >> 5;
    const int gid  = lane >> 2, tig = lane & 3;
    const int wm   = w >> 2,    wn  = w & 3;

    const int m0 = blockIdx.y * 128;
    const int n0 = blockIdx.x * 128;

    const int bpx  = tid >> 1;
    const int kq   = (tid & 1) * 16;
    const int pixg = n0 + bpx;
    const bool px_ok = (pixg < NPIX);
    const unsigned* pb = g_ps2 + (size_t)kq * NPIX + (px_ok ? pixg : 0);

    const int arow  = tid >> 1;
    const int ahalf = tid & 1;
    const unsigned* ap = g_rws + (size_t)(m0 + arow) * 512 + ahalf * 8;
    const int adst = arow * SROW + ahalf * 8;
    const int bdst = (kq ? BH1w : BH0w) + bpx * SROW;

    float acc[4][4][4];
    #pragma unroll
    for (int mi = 0; mi < 4; mi++)
        #pragma unroll
        for (int ni = 0; ni < 4; ni++)
            #pragma unroll
            for (int e = 0; e < 4; e++) acc[mi][ni][e] = 0.f;

    unsigned fv[16];
    auto gatherB = [&](unsigned* dst, int it) {
        const unsigned* p = pb + (size_t)(it * 32) * NPIX;
        #pragma unroll
        for (int i = 0; i < 16; i++)
            dst[i] = px_ok ? p[(size_t)i * NPIX] : 0u;
    };
    auto loadA = [&](unsigned* stage, int it) {
        const unsigned* src = ap + it * 32;
        cp16(stage + AH0w + adst,     src);
        cp16(stage + AH0w + adst + 4, src + 4);
        cp16(stage + AH1w + adst,     src + 16);
        cp16(stage + AH1w + adst + 4, src + 20);
    };

    loadA(sm, 0);
    cp_commit();
    gatherB(fv, 0);

    const int NIT = 512 / 32;   // 16
    int s = 0;
    for (int it = 0; it < NIT; it++) {
        unsigned* base = sm + s * STG;
        {
            uint4* bd = (uint4*)(base + bdst);
            bd[0] = make_uint4(fv[0],  fv[1],  fv[2],  fv[3]);
            bd[1] = make_uint4(fv[4],  fv[5],  fv[6],  fv[7]);
            bd[2] = make_uint4(fv[8],  fv[9],  fv[10], fv[11]);
            bd[3] = make_uint4(fv[12], fv[13], fv[14], fv[15]);
        }
        cp_wait0();
        __syncthreads();

        if (it + 1 < NIT) {
            loadA(sm + (s ^ 1) * STG, it + 1);
            cp_commit();
            gatherB(fv, it + 1);
        }

        mma_tile(base + AH0w, base + AH1w, base + BH0w, base + BH1w,
                 wm, wn, gid, tig, acc);
        s ^= 1;
    }

    #pragma unroll
    for (int mi = 0; mi < 4; mi++) {
        int mA = m0 + wm * 64 + mi * 16 + gid;
        int mB = mA + 8;
        float cA = (mA < KO) ? g_cb[mA] : 0.f;
        float cB2 = (mB < KO) ? g_cb[mB] : 0.f;
        #pragma unroll
        for (int ni = 0; ni < 4; ni++) {
            int pg = n0 + wn * 32 + ni * 8 + 2 * tig;
            #pragma unroll
            for (int e = 0; e < 2; e++) {
                int p = pg + e;
                if (p < NPIX) {
                    int b = p / HW, pp = p - b * HW;
                    if (mA < KO)
                        out[((size_t)b * KO + mA) * HW + pp] = acc[mi][ni][e] + cA;
                    if (mB < KO)
                        out[((size_t)b * KO + mB) * HW + pp] = acc[mi][ni][2 + e] + cB2;
                }
            }
        }
    }
}

// ---------------- launch ----------------------------------------------------
extern "C" void kernel_launch(void* const* d_in, const int* in_sizes, int n_in,
                              void* d_out, int out_size)
{
    const float* feat0 = (const float*)d_in[0];
    const float* feat1 = (const float*)d_in[1];
    const float* w1    = (const float*)d_in[2];
    const float* g1    = (const float*)d_in[3];
    const float* b1    = (const float*)d_in[4];
    const float* m1    = (const float*)d_in[5];
    const float* v1    = (const float*)d_in[6];
    const float* w2    = (const float*)d_in[7];
    const float* g2    = (const float*)d_in[8];
    const float* b2    = (const float*)d_in[9];
    const float* m2    = (const float*)d_in[10];
    const float* v2    = (const float*)d_in[11];
    const float* rw    = (const float*)d_in[12];
    float* out = (float*)d_out;

    cudaFuncSetAttribute(conv2_mma, cudaFuncAttributeMaxDynamicSharedMemorySize, SMEMB);
    cudaFuncSetAttribute(det_mma,   cudaFuncAttributeMaxDynamicSharedMemorySize, SMEMB);

    prep_kernel<<<23040, 256>>>(w1, g1, b1, m1, v1, g2, b2, m2, v2, rw, w2);
    feat0_split<<<46208, 256>>>(feat0);
    conv1_kernel<<<dim3(91, NB), 256>>>(feat1);
    conv2_mma<<<dim3(181, 8), 256, SMEMB>>>();
    det_mma  <<<dim3(181, 5), 256, SMEMB>>>(out);
}